// round 15
// baseline (speedup 1.0000x reference)
#include <cuda_runtime.h>
#include <cuda_fp16.h>
#include <math.h>

#define Bv 2
#define Cv 256
#define Hv 96
#define Wv 192
#define Gv 4
#define Kv 9
#define GC (Cv / Gv)      // 64 channels per group
#define HW (Hv * Wv)      // 18432
#define TPX 16            // pixels per corr block (16 x 1 tile)
#define LPITCH 260        // padded left-tile pitch; multiple of 4 => float4-aligned rows
#define OPITCH 17         // padded out-tile pitch (conflict-free scatter)

// NHWC half scratch for RIGHT feature only (~18.9MB).
__device__ __half g_right_nhwc[(size_t)Bv * Hv * Wv * Cv];

static __device__ __forceinline__ __half2 u32_as_h2(unsigned int u) {
    __half2 h;
    *reinterpret_cast<unsigned int*>(&h) = u;
    return h;
}
static __device__ __forceinline__ unsigned int h2_as_u32(__half2 h) {
    return *reinterpret_cast<unsigned int*>(&h);
}

// ---------------------------------------------------------------------------
// NCHW fp32 -> NHWC fp16 transpose+convert (right feature only).
// Tile: 64 channels x 32 w. grid: (W/32, C/64, B*H), block: 256.
// ---------------------------------------------------------------------------
__global__ __launch_bounds__(256) void nchw_to_nhwc_half_kernel(
    const float* __restrict__ right_in)
{
    __shared__ float tile[64][33];
    const int tid = threadIdx.x;
    const int bh = blockIdx.z;
    const int b = bh / Hv;
    const int h = bh % Hv;

    const float* src = right_in + (size_t)b * Cv * HW + (size_t)h * Wv;
    const int w0 = blockIdx.x * 32;
    const int c0 = blockIdx.y * 64;
    const int tx = tid & 31;
    const int ty = tid >> 5;
#pragma unroll
    for (int i = 0; i < 8; i++) {
        int c = ty + i * 8;
        tile[c][tx] = src[(size_t)(c0 + c) * HW + (w0 + tx)];
    }
    __syncthreads();

    const int r = tid >> 3;        // 0..31  (w within tile)
    const int seg = tid & 7;       // 0..7   (8-channel segment)
    __half hv[8];
#pragma unroll
    for (int j = 0; j < 8; j++)
        hv[j] = __float2half(tile[seg * 8 + j][r]);
    __half* dst = g_right_nhwc + ((size_t)bh * Wv + (w0 + r)) * Cv + c0 + seg * 8;
    *reinterpret_cast<uint4*>(dst) = *reinterpret_cast<uint4*>(hv);
}

// ---------------------------------------------------------------------------
// Correlation kernel. 512-thread block = 16x1 pixel tile, warp = pixel.
// __launch_bounds__(512, 3): 3 blocks/SM + 2-stage k pipeline.
// Gathers are LDG.64 (2 L1 lines each) instead of LDG.128 (4 lines) to avoid
// within-LDG L1tex replay cost. Lane owns ch [4l,4l+4) (lo) and
// [128+4l,128+4l+4) (hi); lo reduces to group l/16, hi to group l/16+2.
// grid: (W/16, H, B)
// ---------------------------------------------------------------------------
__global__ __launch_bounds__(512, 3) void corr_kernel(
    const float* __restrict__ left,
    const float* __restrict__ flow,
    const float* __restrict__ extra,
    float* __restrict__ out)
{
    __shared__ float s_left[TPX * LPITCH];      // ~16.6KB
    __shared__ int4  s_off[TPX * Kv];           // 2.25KB
    __shared__ uint4 s_wgt[TPX * Kv];           // 2.25KB
    __shared__ float s_out[Gv * Kv * OPITCH];   // 2.4KB

    const int tid = threadIdx.x;
    const int b = blockIdx.z;
    const int w0 = blockIdx.x * TPX;
    const int h0 = blockIdx.y;

    // ---- Phase 0: left staging (512 threads; 8 channels each) ----
    {
        const int p = tid & 15;           // pixel in tile
        const int cb = tid >> 4;          // 0..31 channel base
        const float* lp = left + (size_t)b * Cv * HW + (size_t)h0 * Wv + (w0 + p);
#pragma unroll
        for (int i = 0; i < 8; i++) {
            const int c = cb + i * 32;
            s_left[p * LPITCH + c] = lp[(size_t)c * HW];
        }
    }

    // ---- Phase 1: coordinate precompute (144 threads) ----
    if (tid < TPX * Kv) {
        const int pi = tid / Kv;
        const int k = tid - pi * Kv;
        const int w = w0 + pi;
        const int pix = h0 * Wv + w;

        const float fx = flow[(size_t)(b * 2 + 0) * HW + pix];
        const float fy = flow[(size_t)(b * 2 + 1) * HW + pix];
        const float ex = extra[((size_t)(b * Kv + k) * 2 + 0) * HW + pix];
        const float ey = extra[((size_t)(b * Kv + k) * 2 + 1) * HW + pix];
        const float x = (float)w + fx + (float)(k - 4) + ex;
        const float y = (float)h0 + fy + ey;

        const float x0f = floorf(x);
        const float y0f = floorf(y);
        const int ix0 = (int)x0f;
        const int iy0 = (int)y0f;
        const float wx1 = x - x0f;
        const float wy1 = y - y0f;
        const float wx0 = 1.0f - wx1;
        const float wy0 = 1.0f - wy1;

        const bool vx0 = (ix0 >= 0) && (ix0 <= Wv - 1);
        const bool vx1 = (ix0 + 1 >= 0) && (ix0 + 1 <= Wv - 1);
        const bool vy0 = (iy0 >= 0) && (iy0 <= Hv - 1);
        const bool vy1 = (iy0 + 1 >= 0) && (iy0 + 1 <= Hv - 1);

        const int cx0 = min(max(ix0, 0), Wv - 1);
        const int cx1 = min(max(ix0 + 1, 0), Wv - 1);
        const int cy0 = min(max(iy0, 0), Hv - 1);
        const int cy1 = min(max(iy0 + 1, 0), Hv - 1);

        const float w00 = (vx0 && vy0) ? (wx0 * wy0) : 0.0f;
        const float w01 = (vx1 && vy0) ? (wx1 * wy0) : 0.0f;
        const float w10 = (vx0 && vy1) ? (wx0 * wy1) : 0.0f;
        const float w11 = (vx1 && vy1) ? (wx1 * wy1) : 0.0f;

        s_off[tid] = make_int4((cy0 * Wv + cx0) * Cv,
                               (cy0 * Wv + cx1) * Cv,
                               (cy1 * Wv + cx0) * Cv,
                               (cy1 * Wv + cx1) * Cv);
        s_wgt[tid] = make_uint4(h2_as_u32(__float2half2_rn(w00)),
                                h2_as_u32(__float2half2_rn(w01)),
                                h2_as_u32(__float2half2_rn(w10)),
                                h2_as_u32(__float2half2_rn(w11)));
    }
    __syncthreads();

    // ---- Phase 2: gather + correlate (2-stage pipeline over k) ----
    const int lane = tid & 31;
    const int p = tid >> 5;                  // 0..15 pixel in tile (warp = pixel)

    float Lf[8];
    {
        const float4 A = *reinterpret_cast<const float4*>(&s_left[p * LPITCH + lane * 4]);
        const float4 B = *reinterpret_cast<const float4*>(&s_left[p * LPITCH + 128 + lane * 4]);
        Lf[0] = A.x; Lf[1] = A.y; Lf[2] = A.z; Lf[3] = A.w;
        Lf[4] = B.x; Lf[5] = B.y; Lf[6] = B.z; Lf[7] = B.w;
    }

    const __half* rbase_lo = g_right_nhwc + (size_t)b * HW * Cv + lane * 4;
    const __half* rbase_hi = rbase_lo + 128;

    uint4 wgc = s_wgt[p * Kv];
    uint2 lc[4], hc[4];
    {
        const int4 off = s_off[p * Kv];
        lc[0] = *reinterpret_cast<const uint2*>(rbase_lo + off.x);
        lc[1] = *reinterpret_cast<const uint2*>(rbase_lo + off.y);
        lc[2] = *reinterpret_cast<const uint2*>(rbase_lo + off.z);
        lc[3] = *reinterpret_cast<const uint2*>(rbase_lo + off.w);
        hc[0] = *reinterpret_cast<const uint2*>(rbase_hi + off.x);
        hc[1] = *reinterpret_cast<const uint2*>(rbase_hi + off.y);
        hc[2] = *reinterpret_cast<const uint2*>(rbase_hi + off.z);
        hc[3] = *reinterpret_cast<const uint2*>(rbase_hi + off.w);
    }

#pragma unroll
    for (int k = 0; k < Kv; k++) {
        uint2 ln[4], hn[4];
        uint4 wgn;
        if (k < Kv - 1) {
            const int4 off = s_off[p * Kv + k + 1];
            wgn = s_wgt[p * Kv + k + 1];
            ln[0] = *reinterpret_cast<const uint2*>(rbase_lo + off.x);
            ln[1] = *reinterpret_cast<const uint2*>(rbase_lo + off.y);
            ln[2] = *reinterpret_cast<const uint2*>(rbase_lo + off.z);
            ln[3] = *reinterpret_cast<const uint2*>(rbase_lo + off.w);
            hn[0] = *reinterpret_cast<const uint2*>(rbase_hi + off.x);
            hn[1] = *reinterpret_cast<const uint2*>(rbase_hi + off.y);
            hn[2] = *reinterpret_cast<const uint2*>(rbase_hi + off.z);
            hn[3] = *reinterpret_cast<const uint2*>(rbase_hi + off.w);
        }

        const __half2 w00 = u32_as_h2(wgc.x);
        const __half2 w01 = u32_as_h2(wgc.y);
        const __half2 w10 = u32_as_h2(wgc.z);
        const __half2 w11 = u32_as_h2(wgc.w);

        float lo_sum, hi_sum;
        {
            __half2 v = __hmul2(w00, u32_as_h2(lc[0].x));
            v = __hfma2(w01, u32_as_h2(lc[1].x), v);
            v = __hfma2(w10, u32_as_h2(lc[2].x), v);
            v = __hfma2(w11, u32_as_h2(lc[3].x), v);
            float2 f = __half22float2(v);
            lo_sum = Lf[0] * f.x + Lf[1] * f.y;

            v = __hmul2(w00, u32_as_h2(lc[0].y));
            v = __hfma2(w01, u32_as_h2(lc[1].y), v);
            v = __hfma2(w10, u32_as_h2(lc[2].y), v);
            v = __hfma2(w11, u32_as_h2(lc[3].y), v);
            f = __half22float2(v);
            lo_sum = fmaf(Lf[2], f.x, lo_sum);
            lo_sum = fmaf(Lf[3], f.y, lo_sum);

            v = __hmul2(w00, u32_as_h2(hc[0].x));
            v = __hfma2(w01, u32_as_h2(hc[1].x), v);
            v = __hfma2(w10, u32_as_h2(hc[2].x), v);
            v = __hfma2(w11, u32_as_h2(hc[3].x), v);
            f = __half22float2(v);
            hi_sum = Lf[4] * f.x + Lf[5] * f.y;

            v = __hmul2(w00, u32_as_h2(hc[0].y));
            v = __hfma2(w01, u32_as_h2(hc[1].y), v);
            v = __hfma2(w10, u32_as_h2(hc[2].y), v);
            v = __hfma2(w11, u32_as_h2(hc[3].y), v);
            f = __half22float2(v);
            hi_sum = fmaf(Lf[6], f.x, hi_sum);
            hi_sum = fmaf(Lf[7], f.y, hi_sum);
        }

        // 16-lane reductions (lo -> group l/16; hi -> group l/16 + 2)
        lo_sum += __shfl_xor_sync(0xffffffffu, lo_sum, 8);
        hi_sum += __shfl_xor_sync(0xffffffffu, hi_sum, 8);
        lo_sum += __shfl_xor_sync(0xffffffffu, lo_sum, 4);
        hi_sum += __shfl_xor_sync(0xffffffffu, hi_sum, 4);
        lo_sum += __shfl_xor_sync(0xffffffffu, lo_sum, 2);
        hi_sum += __shfl_xor_sync(0xffffffffu, hi_sum, 2);
        lo_sum += __shfl_xor_sync(0xffffffffu, lo_sum, 1);
        hi_sum += __shfl_xor_sync(0xffffffffu, hi_sum, 1);

        if ((lane & 15) == 0) {
            const int g = lane >> 4;  // 0 or 1
            s_out[(g * Kv + k) * OPITCH + p] = lo_sum * (1.0f / GC);
            s_out[((g + 2) * Kv + k) * OPITCH + p] = hi_sum * (1.0f / GC);
        }

        if (k < Kv - 1) {
#pragma unroll
            for (int c = 0; c < 4; c++) { lc[c] = ln[c]; hc[c] = hn[c]; }
            wgc = wgn;
        }
    }
    __syncthreads();

    // ---- Phase 3: coalesced output stores ----
    {
#pragma unroll
        for (int it = 0; it < 2; it++) {
            const int i = tid + it * 512;
            if (i < Gv * Kv * TPX) {
                const int row = i >> 4;       // g*Kv+k
                const int col = i & 15;       // pixel
                out[((size_t)b * Gv * Kv + row) * HW + (size_t)h0 * Wv + (w0 + col)] =
                    s_out[row * OPITCH + col];
            }
        }
    }
}

extern "C" void kernel_launch(void* const* d_in, const int* in_sizes, int n_in,
                              void* d_out, int out_size) {
    const float* left  = (const float*)d_in[0];
    const float* right = (const float*)d_in[1];
    const float* flow  = (const float*)d_in[2];
    const float* extra = (const float*)d_in[3];
    float* out = (float*)d_out;

    {
        dim3 grid(Wv / 32, Cv / 64, Bv * Hv);
        nchw_to_nhwc_half_kernel<<<grid, 256>>>(right);
    }
    {
        dim3 grid(Wv / TPX, Hv, Bv);
        corr_kernel<<<grid, 512>>>(left, flow, extra, out);
    }
}

// round 16
// speedup vs baseline: 1.0855x; 1.0855x over previous
#include <cuda_runtime.h>
#include <cuda_fp16.h>
#include <math.h>

#define Bv 2
#define Cv 256
#define Hv 96
#define Wv 192
#define Gv 4
#define Kv 9
#define GC (Cv / Gv)      // 64 channels per group
#define HW (Hv * Wv)      // 18432
#define TPX 16            // pixels per corr block (16 x 1 tile)
#define LPITCH 260        // padded left-tile pitch; multiple of 4 => float4-aligned rows
#define OPITCH 17         // padded out-tile pitch (conflict-free scatter)

// NHWC half scratch for RIGHT feature only (~18.9MB).
__device__ __half g_right_nhwc[(size_t)Bv * Hv * Wv * Cv];

static __device__ __forceinline__ __half2 u32_as_h2(unsigned int u) {
    __half2 h;
    *reinterpret_cast<unsigned int*>(&h) = u;
    return h;
}
static __device__ __forceinline__ unsigned int h2_as_u32(__half2 h) {
    return *reinterpret_cast<unsigned int*>(&h);
}

// ---------------------------------------------------------------------------
// NCHW fp32 -> NHWC fp16 transpose+convert (right feature only).
// Tile: 64 channels x 32 w. grid: (W/32, C/64, B*H), block: 256.
// ---------------------------------------------------------------------------
__global__ __launch_bounds__(256) void nchw_to_nhwc_half_kernel(
    const float* __restrict__ right_in)
{
    __shared__ float tile[64][33];
    const int tid = threadIdx.x;
    const int bh = blockIdx.z;
    const int b = bh / Hv;
    const int h = bh % Hv;

    const float* src = right_in + (size_t)b * Cv * HW + (size_t)h * Wv;
    const int w0 = blockIdx.x * 32;
    const int c0 = blockIdx.y * 64;
    const int tx = tid & 31;
    const int ty = tid >> 5;
#pragma unroll
    for (int i = 0; i < 8; i++) {
        int c = ty + i * 8;
        tile[c][tx] = src[(size_t)(c0 + c) * HW + (w0 + tx)];
    }
    __syncthreads();

    const int r = tid >> 3;        // 0..31  (w within tile)
    const int seg = tid & 7;       // 0..7   (8-channel segment)
    __half hv[8];
#pragma unroll
    for (int j = 0; j < 8; j++)
        hv[j] = __float2half(tile[seg * 8 + j][r]);
    __half* dst = g_right_nhwc + ((size_t)bh * Wv + (w0 + r)) * Cv + c0 + seg * 8;
    *reinterpret_cast<uint4*>(dst) = *reinterpret_cast<uint4*>(hv);
}

// ---------------------------------------------------------------------------
// Correlation kernel (R11 shape). 512-thread block = 16x1 pixel tile,
// warp = pixel. __launch_bounds__(512, 3): 3 blocks/SM + 2-stage k pipeline.
// Gathers are warp-wide LDG.128 (512B contiguous per corner).
// grid: (W/16, H, B)
// ---------------------------------------------------------------------------
__global__ __launch_bounds__(512, 3) void corr_kernel(
    const float* __restrict__ left,
    const float* __restrict__ flow,
    const float* __restrict__ extra,
    float* __restrict__ out)
{
    __shared__ float s_left[TPX * LPITCH];      // ~16.6KB
    __shared__ int4  s_off[TPX * Kv];           // 2.25KB
    __shared__ uint4 s_wgt[TPX * Kv];           // 2.25KB
    __shared__ float s_out[Gv * Kv * OPITCH];   // 2.4KB

    const int tid = threadIdx.x;
    const int b = blockIdx.z;
    const int w0 = blockIdx.x * TPX;
    const int h0 = blockIdx.y;

    // ---- Phase 0: left staging (512 threads; 8 channels each) ----
    {
        const int p = tid & 15;           // pixel in tile
        const int cb = tid >> 4;          // 0..31 channel base
        const float* lp = left + (size_t)b * Cv * HW + (size_t)h0 * Wv + (w0 + p);
#pragma unroll
        for (int i = 0; i < 8; i++) {
            const int c = cb + i * 32;
            s_left[p * LPITCH + c] = lp[(size_t)c * HW];
        }
    }

    // ---- Phase 1: coordinate precompute (144 threads) ----
    if (tid < TPX * Kv) {
        const int pi = tid / Kv;
        const int k = tid - pi * Kv;
        const int w = w0 + pi;
        const int pix = h0 * Wv + w;

        const float fx = flow[(size_t)(b * 2 + 0) * HW + pix];
        const float fy = flow[(size_t)(b * 2 + 1) * HW + pix];
        const float ex = extra[((size_t)(b * Kv + k) * 2 + 0) * HW + pix];
        const float ey = extra[((size_t)(b * Kv + k) * 2 + 1) * HW + pix];
        const float x = (float)w + fx + (float)(k - 4) + ex;
        const float y = (float)h0 + fy + ey;

        const float x0f = floorf(x);
        const float y0f = floorf(y);
        const int ix0 = (int)x0f;
        const int iy0 = (int)y0f;
        const float wx1 = x - x0f;
        const float wy1 = y - y0f;
        const float wx0 = 1.0f - wx1;
        const float wy0 = 1.0f - wy1;

        const bool vx0 = (ix0 >= 0) && (ix0 <= Wv - 1);
        const bool vx1 = (ix0 + 1 >= 0) && (ix0 + 1 <= Wv - 1);
        const bool vy0 = (iy0 >= 0) && (iy0 <= Hv - 1);
        const bool vy1 = (iy0 + 1 >= 0) && (iy0 + 1 <= Hv - 1);

        const int cx0 = min(max(ix0, 0), Wv - 1);
        const int cx1 = min(max(ix0 + 1, 0), Wv - 1);
        const int cy0 = min(max(iy0, 0), Hv - 1);
        const int cy1 = min(max(iy0 + 1, 0), Hv - 1);

        const float w00 = (vx0 && vy0) ? (wx0 * wy0) : 0.0f;
        const float w01 = (vx1 && vy0) ? (wx1 * wy0) : 0.0f;
        const float w10 = (vx0 && vy1) ? (wx0 * wy1) : 0.0f;
        const float w11 = (vx1 && vy1) ? (wx1 * wy1) : 0.0f;

        s_off[tid] = make_int4((cy0 * Wv + cx0) * Cv,
                               (cy0 * Wv + cx1) * Cv,
                               (cy1 * Wv + cx0) * Cv,
                               (cy1 * Wv + cx1) * Cv);
        s_wgt[tid] = make_uint4(h2_as_u32(__float2half2_rn(w00)),
                                h2_as_u32(__float2half2_rn(w01)),
                                h2_as_u32(__float2half2_rn(w10)),
                                h2_as_u32(__float2half2_rn(w11)));
    }
    __syncthreads();

    // ---- Phase 2: gather + correlate (2-stage pipeline over k) ----
    const int lane = tid & 31;
    const int p = tid >> 5;                  // 0..15 pixel in tile (warp = pixel)

    float Lf[8];
    {
        const float4* lp = (const float4*)&s_left[p * LPITCH + lane * 8];
        float4 A = lp[0], B = lp[1];
        Lf[0] = A.x; Lf[1] = A.y; Lf[2] = A.z; Lf[3] = A.w;
        Lf[4] = B.x; Lf[5] = B.y; Lf[6] = B.z; Lf[7] = B.w;
    }

    const __half* rbase = g_right_nhwc + (size_t)b * HW * Cv + lane * 8;

    uint4 wg_cur = s_wgt[p * Kv];
    uint4 a0, a1, a2, a3;
    {
        const int4 off = s_off[p * Kv];
        a0 = *reinterpret_cast<const uint4*>(rbase + off.x);
        a1 = *reinterpret_cast<const uint4*>(rbase + off.y);
        a2 = *reinterpret_cast<const uint4*>(rbase + off.z);
        a3 = *reinterpret_cast<const uint4*>(rbase + off.w);
    }

#pragma unroll
    for (int k = 0; k < Kv; k++) {
        uint4 b0, b1, b2, b3, wg_nxt;
        if (k < Kv - 1) {
            const int4 off = s_off[p * Kv + k + 1];
            wg_nxt = s_wgt[p * Kv + k + 1];
            b0 = *reinterpret_cast<const uint4*>(rbase + off.x);
            b1 = *reinterpret_cast<const uint4*>(rbase + off.y);
            b2 = *reinterpret_cast<const uint4*>(rbase + off.z);
            b3 = *reinterpret_cast<const uint4*>(rbase + off.w);
        }

        const __half2 w00 = u32_as_h2(wg_cur.x);
        const __half2 w01 = u32_as_h2(wg_cur.y);
        const __half2 w10 = u32_as_h2(wg_cur.z);
        const __half2 w11 = u32_as_h2(wg_cur.w);

        const __half2* pa = (const __half2*)&a0;
        const __half2* pc = (const __half2*)&a1;
        const __half2* pd = (const __half2*)&a2;
        const __half2* pe = (const __half2*)&a3;

        float s0 = 0.0f, s1 = 0.0f;
#pragma unroll
        for (int j = 0; j < 4; j++) {
            __half2 v = __hmul2(w00, pa[j]);
            v = __hfma2(w01, pc[j], v);
            v = __hfma2(w10, pd[j], v);
            v = __hfma2(w11, pe[j], v);
            float2 f = __half22float2(v);
            s0 = fmaf(Lf[2 * j], f.x, s0);
            s1 = fmaf(Lf[2 * j + 1], f.y, s1);
        }
        float s = s0 + s1;

        // reduce across the 8 threads of this channel-group (contiguous lanes)
        s += __shfl_xor_sync(0xffffffffu, s, 4);
        s += __shfl_xor_sync(0xffffffffu, s, 2);
        s += __shfl_xor_sync(0xffffffffu, s, 1);

        if ((lane & 7) == 0) {
            const int g = lane >> 3;  // 0..3
            s_out[(g * Kv + k) * OPITCH + p] = s * (1.0f / GC);
        }

        if (k < Kv - 1) {
            a0 = b0; a1 = b1; a2 = b2; a3 = b3;
            wg_cur = wg_nxt;
        }
    }
    __syncthreads();

    // ---- Phase 3: coalesced output stores ----
    {
#pragma unroll
        for (int it = 0; it < 2; it++) {
            const int i = tid + it * 512;
            if (i < Gv * Kv * TPX) {
                const int row = i >> 4;       // g*Kv+k
                const int col = i & 15;       // pixel
                out[((size_t)b * Gv * Kv + row) * HW + (size_t)h0 * Wv + (w0 + col)] =
                    s_out[row * OPITCH + col];
            }
        }
    }
}

extern "C" void kernel_launch(void* const* d_in, const int* in_sizes, int n_in,
                              void* d_out, int out_size) {
    const float* left  = (const float*)d_in[0];
    const float* right = (const float*)d_in[1];
    const float* flow  = (const float*)d_in[2];
    const float* extra = (const float*)d_in[3];
    float* out = (float*)d_out;

    // Request minimal shared-memory carveout for corr so the unified L1D keeps
    // maximum capacity for the gather working set. Host-side, deterministic,
    // no allocation; harmless if the driver ignores it.
    static bool carveout_set = false;
    if (!carveout_set) {
        cudaFuncSetAttribute(corr_kernel,
                             cudaFuncAttributePreferredSharedMemoryCarveout, 34);
        carveout_set = true;
    }

    {
        dim3 grid(Wv / 32, Cv / 64, Bv * Hv);
        nchw_to_nhwc_half_kernel<<<grid, 256>>>(right);
    }
    {
        dim3 grid(Wv / TPX, Hv, Bv);
        corr_kernel<<<grid, 512>>>(left, flow, extra, out);
    }
}